// round 5
// baseline (speedup 1.0000x reference)
#include <cuda_runtime.h>
#include <cuda_bf16.h>
#include <math.h>

// Problem constants: B=32, N=128, D=256, H=8, DK=32
typedef unsigned int u32;
typedef __nv_bfloat16 bf16;

#define NCTA 148
#define SMEM_TOTAL 84480   // sc(66048) + kv(16384) + cmask(2048)

// ---------------- scratch (static device globals; no allocation) -------------
__device__ __align__(16) float g_fA[1024 * 256];
__device__ __align__(16) float g_fB[1024 * 256];
__device__ __align__(16) float g_conn[8 * 128 * 128];
__device__ __align__(16) float g_q[4096 * 256];     // [B,H,N,DK]
__device__ __align__(16) float g_k[4096 * 256];
__device__ __align__(16) float g_v[4096 * 256];
__device__ __align__(16) bf16 g_h1hi[4096 * 256];
__device__ __align__(16) bf16 g_h1lo[4096 * 256];
__device__ __align__(16) bf16 g_xmhi[4096 * 256];
__device__ __align__(16) bf16 g_xmlo[4096 * 256];
__device__ __align__(16) bf16 g_aohi[4096 * 256];
__device__ __align__(16) bf16 g_aolo[4096 * 256];

// grid barrier state (zero-init; generation is monotonic across graph replays)
__device__ unsigned g_barCount[4];
__device__ volatile unsigned g_barGen[4];

struct Params {
    const float *x, *gu, *mw, *fcw, *fcb, *fccw, *fccb;
    const float *wq, *bq, *wk, *bk, *wv, *bv, *ow, *ob;
    const float *w1, *b1, *w2, *b2;
    float* out;
};

__device__ __forceinline__ void gridBarrier(int i, int nC) {
    __syncthreads();
    if (threadIdx.x == 0) {
        __threadfence();
        unsigned gen = g_barGen[i];
        if (atomicAdd(&g_barCount[i], 1) == (unsigned)(nC - 1)) {
            g_barCount[i] = 0;
            __threadfence();
            g_barGen[i] = gen + 1;
        } else {
            while (g_barGen[i] == gen) __nanosleep(64);
            __threadfence();
        }
    }
    __syncthreads();
}

__device__ __forceinline__ float gelu_tanh(float x) {
    float x3 = x * x * x;
    float t = tanhf(0.7978845608028654f * (x + 0.044715f * x3));
    return 0.5f * x * (1.0f + t);
}

__device__ __forceinline__ void split_bf16(float v, bf16& h, bf16& l) {
    h = __float2bfloat16_rn(v);
    l = __float2bfloat16_rn(v - __bfloat162float(h));
}

__device__ __forceinline__ void cvt4(float4 v, uint2& hi, uint2& lo) {
    bf16 h0, l0, h1, l1, h2, l2, h3, l3;
    split_bf16(v.x, h0, l0); split_bf16(v.y, h1, l1);
    split_bf16(v.z, h2, l2); split_bf16(v.w, h3, l3);
    __nv_bfloat162 a, b, c, d;
    a.x = h0; a.y = h1; b.x = h2; b.y = h3;
    c.x = l0; c.y = l1; d.x = l2; d.y = l3;
    hi.x = *(u32*)&a; hi.y = *(u32*)&b;
    lo.x = *(u32*)&c; lo.y = *(u32*)&d;
}

#define LDSM4(r, addr)                                                        \
    asm volatile("ldmatrix.sync.aligned.m8n8.x4.shared.b16 {%0,%1,%2,%3}, [%4];" \
                 : "=r"(r[0]), "=r"(r[1]), "=r"(r[2]), "=r"(r[3]) : "r"(addr))

#define LDSM4T(r, addr)                                                       \
    asm volatile("ldmatrix.sync.aligned.m8n8.x4.trans.shared.b16 {%0,%1,%2,%3}, [%4];" \
                 : "=r"(r[0]), "=r"(r[1]), "=r"(r[2]), "=r"(r[3]) : "r"(addr))

#define MMA16816(d, a, b)                                                     \
    asm volatile("mma.sync.aligned.m16n8k16.row.col.f32.bf16.bf16.f32 "       \
                 "{%0,%1,%2,%3}, {%4,%5,%6,%7}, {%8,%9}, {%0,%1,%2,%3};"      \
                 : "+f"(d[0]), "+f"(d[1]), "+f"(d[2]), "+f"(d[3])             \
                 : "r"(a[0]), "r"(a[1]), "r"(a[2]), "r"(a[3]),                \
                   "r"(b[0]), "r"(b[1]))

// ---------------- GEMM tile: 64x64 out, k=256, split-bf16 (3 MMAs) -----------
// A modes: 0 fp32 row-major, 1 fp32 memory_w gather, 2 bf16 planes.
// W: always fp32, converted to hi/lo planes inline during staging.
struct GJ {
    const float* Af;
    const bf16 *Ahi, *Alo;
    const float* Wf;
    const float* bias;
    float* Cf;
    bf16 *Chi, *Clo;
    int rowBase, colBase;
    int aMode, act, storeMode;   // storeMode: 0 fp32, 1 planes, 2 QKV permute
};

__device__ __noinline__ void gemmTile(const GJ J, char* smemRaw)
{
    bf16* sAhi = (bf16*)smemRaw;          // 2 bufs x 64x40
    bf16* sAlo = sAhi + 2 * 64 * 40;
    bf16* sWhi = sAlo + 2 * 64 * 40;      // 2 bufs x 32x72
    bf16* sWlo = sWhi + 2 * 32 * 72;

    int t = threadIdx.x;
    int warp = t >> 5, lane = t & 31;
    int wm = warp >> 1, wn = warp & 1;
    int g = lane >> 3, r = lane & 7;

    u32 sAhiB = (u32)__cvta_generic_to_shared(sAhi);
    u32 sAloB = (u32)__cvta_generic_to_shared(sAlo);
    u32 sWhiB = (u32)__cvta_generic_to_shared(sWhi);
    u32 sWloB = (u32)__cvta_generic_to_shared(sWlo);
    const u32 ABUF = 64 * 40 * 2;   // bytes
    const u32 WBUF = 32 * 72 * 2;

    int arow = t >> 3, aseg = t & 7;
    int arow2 = (t + 256) >> 3, aseg2 = (t + 256) & 7;
    int prow = t >> 2, pseg = t & 3;
    int wrow = t >> 3, wseg = t & 7;

    float4 fa0, fa1, fw0, fw1;
    uint4 pah, pal;

    auto loadTile = [&](int kt) {
        if (J.aMode == 2) {
            int gidx = (J.rowBase + prow) * 256 + kt + pseg * 8;
            pah = *(const uint4*)&J.Ahi[gidx];
            pal = *(const uint4*)&J.Alo[gidx];
        } else if (J.aMode == 0) {
            fa0 = *(const float4*)&J.Af[(J.rowBase + arow) * 256 + kt + aseg * 4];
            fa1 = *(const float4*)&J.Af[(J.rowBase + arow2) * 256 + kt + aseg2 * 4];
        } else {
            int rr = J.rowBase + arow;   int h = rr >> 7,  n = rr & 127;
            int rr2 = J.rowBase + arow2; int h2 = rr2 >> 7, n2 = rr2 & 127;
            fa0 = *(const float4*)&J.Af[n * 2048 + h * 256 + kt + aseg * 4];
            fa1 = *(const float4*)&J.Af[n2 * 2048 + h2 * 256 + kt + aseg2 * 4];
        }
        const float* wp = &J.Wf[(kt + wrow) * 256 + J.colBase + wseg * 8];
        fw0 = *(const float4*)wp;
        fw1 = *(const float4*)(wp + 4);
    };

    auto storeTile = [&](int bb) {
        if (J.aMode == 2) {
            int soff = bb * 2560 + prow * 40 + pseg * 8;
            *(uint4*)&sAhi[soff] = pah;
            *(uint4*)&sAlo[soff] = pal;
        } else {
            uint2 hi, lo;
            cvt4(fa0, hi, lo);
            *(uint2*)&sAhi[bb * 2560 + arow * 40 + aseg * 4] = hi;
            *(uint2*)&sAlo[bb * 2560 + arow * 40 + aseg * 4] = lo;
            cvt4(fa1, hi, lo);
            *(uint2*)&sAhi[bb * 2560 + arow2 * 40 + aseg2 * 4] = hi;
            *(uint2*)&sAlo[bb * 2560 + arow2 * 40 + aseg2 * 4] = lo;
        }
        uint2 hi, lo;
        cvt4(fw0, hi, lo);
        *(uint2*)&sWhi[bb * 2304 + wrow * 72 + wseg * 8] = hi;
        *(uint2*)&sWlo[bb * 2304 + wrow * 72 + wseg * 8] = lo;
        cvt4(fw1, hi, lo);
        *(uint2*)&sWhi[bb * 2304 + wrow * 72 + wseg * 8 + 4] = hi;
        *(uint2*)&sWlo[bb * 2304 + wrow * 72 + wseg * 8 + 4] = lo;
    };

    float acc[4][4];
    #pragma unroll
    for (int nt = 0; nt < 4; nt++)
        #pragma unroll
        for (int i = 0; i < 4; i++) acc[nt][i] = 0.0f;

    __syncthreads();  // protect smem from previous job's readers
    loadTile(0);
    storeTile(0);
    __syncthreads();

    #pragma unroll
    for (int it = 0; it < 8; it++) {
        int bb = it & 1;
        if (it < 7) loadTile((it + 1) * 32);

        #pragma unroll
        for (int ks = 0; ks < 32; ks += 16) {
            u32 ah[4], al[4], bh[2][4], bl[2][4];
            {
                int rowA = wm * 16 + r + ((g & 1) << 3);
                int kcol = ks + ((g >> 1) << 3);
                u32 off = bb * ABUF + (u32)(rowA * 40 + kcol) * 2;
                LDSM4(ah, sAhiB + off);
                LDSM4(al, sAloB + off);
            }
            #pragma unroll
            for (int np = 0; np < 2; np++) {
                int krow = ks + r + ((g & 1) << 3);
                int ncol = wn * 32 + np * 16 + ((g >> 1) << 3);
                u32 off = bb * WBUF + (u32)(krow * 72 + ncol) * 2;
                LDSM4T(bh[np], sWhiB + off);
                LDSM4T(bl[np], sWloB + off);
            }
            #pragma unroll
            for (int nt = 0; nt < 4; nt++) {
                const u32* Bh = &bh[nt >> 1][(nt & 1) * 2];
                const u32* Bl = &bl[nt >> 1][(nt & 1) * 2];
                MMA16816(acc[nt], ah, Bh);
                MMA16816(acc[nt], ah, Bl);
                MMA16816(acc[nt], al, Bh);
            }
        }
        __syncthreads();
        if (it < 7) {
            storeTile(1 - bb);
            __syncthreads();
        }
    }

    #pragma unroll
    for (int nt = 0; nt < 4; nt++) {
        int row0 = J.rowBase + wm * 16 + (lane >> 2);
        int col0 = J.colBase + wn * 32 + nt * 8 + (lane & 3) * 2;
        float bv0 = J.bias ? J.bias[col0] : 0.0f;
        float bv1 = J.bias ? J.bias[col0 + 1] : 0.0f;
        #pragma unroll
        for (int half = 0; half < 2; half++) {
            int row = row0 + half * 8;
            float v0 = acc[nt][half * 2 + 0] + bv0;
            float v1 = acc[nt][half * 2 + 1] + bv1;
            if (J.act) { v0 = gelu_tanh(v0); v1 = gelu_tanh(v1); }
            if (J.storeMode == 0) {
                *(float2*)&J.Cf[row * 256 + col0] = make_float2(v0, v1);
            } else if (J.storeMode == 1) {
                bf16 h0, l0, h1, l1;
                split_bf16(v0, h0, l0);
                split_bf16(v1, h1, l1);
                __nv_bfloat162 H; H.x = h0; H.y = h1;
                __nv_bfloat162 L; L.x = l0; L.y = l1;
                *(__nv_bfloat162*)&J.Chi[row * 256 + col0] = H;
                *(__nv_bfloat162*)&J.Clo[row * 256 + col0] = L;
            } else {
                int b = row >> 7, n = row & 127;
                int h = col0 >> 5, dk = col0 & 31;
                *(float2*)&J.Cf[(((b * 8 + h) * 128 + n) * 32) + dk] = make_float2(v0, v1);
            }
        }
    }
}

// ---------------- connection mask job: 32i x 32j tile, 256 threads -----------
__device__ __noinline__ void connJob(int cid, const Params& P, char* smemRaw)
{
    float (*Aj)[33] = (float(*)[33])smemRaw;
    float (*Bi)[33] = (float(*)[33])(smemRaw + 32 * 33 * 4);
    float* Cs0 = (float*)(smemRaw + 2 * 32 * 33 * 4);
    float* Cs1 = Cs0 + 256;

    int h = cid >> 4;
    int ibase = ((cid >> 2) & 3) * 32;
    int jbase = (cid & 3) * 32;
    int t = threadIdx.x;
    int tx = t & 15, ty = t >> 4;

    __syncthreads();  // protect smem from previous job's readers
    Cs0[t] = P.fccw[2 * t];
    Cs1[t] = P.fccw[2 * t + 1];

    float l0[2][2] = {{0.f, 0.f}, {0.f, 0.f}};
    float l1[2][2] = {{0.f, 0.f}, {0.f, 0.f}};

    for (int d0 = 0; d0 < 256; d0 += 32) {
        if (d0) __syncthreads();
        int jr = t >> 3, c = (t & 7) * 4;
        float4 va = *(const float4*)&g_fA[(h * 128 + jbase + jr) * 256 + d0 + c];
        Aj[jr][c] = va.x; Aj[jr][c + 1] = va.y; Aj[jr][c + 2] = va.z; Aj[jr][c + 3] = va.w;
        float4 vb = *(const float4*)&g_fB[(h * 128 + ibase + jr) * 256 + d0 + c];
        float4 o = *(const float4*)&P.fcb[d0 + c];
        Bi[jr][c] = vb.x + o.x; Bi[jr][c + 1] = vb.y + o.y;
        Bi[jr][c + 2] = vb.z + o.z; Bi[jr][c + 3] = vb.w + o.w;
        __syncthreads();

        #pragma unroll
        for (int dd = 0; dd < 32; dd++) {
            float a0 = Aj[tx * 2][dd], a1 = Aj[tx * 2 + 1][dd];
            float b0 = Bi[ty * 2][dd], b1 = Bi[ty * 2 + 1][dd];
            float c0v = Cs0[d0 + dd], c1v = Cs1[d0 + dd];
            float r00 = fmaxf(a0 + b0, 0.f), r10 = fmaxf(a1 + b0, 0.f);
            float r01 = fmaxf(a0 + b1, 0.f), r11 = fmaxf(a1 + b1, 0.f);
            l0[0][0] = fmaf(r00, c0v, l0[0][0]); l1[0][0] = fmaf(r00, c1v, l1[0][0]);
            l0[0][1] = fmaf(r10, c0v, l0[0][1]); l1[0][1] = fmaf(r10, c1v, l1[0][1]);
            l0[1][0] = fmaf(r01, c0v, l0[1][0]); l1[1][0] = fmaf(r01, c1v, l1[1][0]);
            l0[1][1] = fmaf(r11, c0v, l0[1][1]); l1[1][1] = fmaf(r11, c1v, l1[1][1]);
        }
    }

    float cb0 = P.fccb[0], cb1 = P.fccb[1];
    #pragma unroll
    for (int ii = 0; ii < 2; ii++) {
        int i = ibase + ty * 2 + ii;
        #pragma unroll
        for (int jj = 0; jj < 2; jj++) {
            int j = jbase + tx * 2 + jj;
            int idx = (h * 128 + i) * 128 + j;
            float2 u2 = *(const float2*)&P.gu[idx * 2];
            float gg0 = -logf(-logf(u2.x + 1e-10f) + 1e-10f);
            float gg1 = -logf(-logf(u2.y + 1e-10f) + 1e-10f);
            g_conn[idx] = ((l1[ii][jj] + cb1 + gg1) > (l0[ii][jj] + cb0 + gg0)) ? 1.0f : 0.0f;
        }
    }
}

// ---------------- attention job: one (b,h), 256 threads ----------------------
// row = t>>1, j-half = t&1; pair combine via shfl_xor(.,1).
__device__ __noinline__ void attnJob(int bid, char* smemRaw)
{
    float* sc = (float*)smemRaw;          // 128*129
    float* kv = sc + 128 * 129;           // 4096
    u32* cmask = (u32*)(kv + 4096);       // 512

    int t = threadIdx.x, w = t >> 5, lane = t & 31;
    int b = bid >> 3, h = bid & 7;
    __syncthreads();  // protect smem from previous job's readers

    const float* cr = g_conn + h * 16384;
    for (int i0b = 0; i0b < 128; i0b += 2) {
        int i0 = i0b + (w >> 2);
        float c = cr[i0 * 128 + (w & 3) * 32 + lane];
        u32 bal = __ballot_sync(0xffffffffu, c > 0.5f);
        if (lane == 0) cmask[i0 * 4 + (w & 3)] = bal;
    }
    for (int idx = t; idx < 4096; idx += 256) kv[idx] = g_k[bid * 4096 + idx];
    __syncthreads();

    int r = t >> 1, half = t & 1;
    float4 qr[8];
    const float4* qp = (const float4*)(g_q + (bid * 128 + r) * 32);
    #pragma unroll
    for (int d = 0; d < 8; d++) qr[d] = qp[d];
    u32 m0 = cmask[r * 4 + half * 2], m1 = cmask[r * 4 + half * 2 + 1];

    const float scale = 0.17677669529663687f;  // 1/sqrt(32)
    const float4* kv4 = (const float4*)kv;
    float mx = -INFINITY;

    #pragma unroll
    for (int w2 = 0; w2 < 2; w2++) {
        u32 word = w2 ? m1 : m0;
        for (int jj = 0; jj < 32; jj++) {
            int j = half * 64 + w2 * 32 + jj;
            float s;
            if ((word >> jj) & 1u) {
                float a0 = 0.f, a1 = 0.f, a2 = 0.f, a3 = 0.f;
                #pragma unroll
                for (int d = 0; d < 8; d++) {
                    float4 kk4 = kv4[j * 8 + d];
                    a0 = fmaf(qr[d].x, kk4.x, a0);
                    a1 = fmaf(qr[d].y, kk4.y, a1);
                    a2 = fmaf(qr[d].z, kk4.z, a2);
                    a3 = fmaf(qr[d].w, kk4.w, a3);
                }
                s = ((a0 + a1) + (a2 + a3)) * scale;
                mx = fmaxf(mx, s);
            } else {
                s = -INFINITY;
            }
            sc[r * 129 + j] = s;
        }
    }
    mx = fmaxf(mx, __shfl_xor_sync(0xffffffffu, mx, 1));
    __syncthreads();  // all K reads done

    for (int idx = t; idx < 4096; idx += 256) kv[idx] = g_v[bid * 4096 + idx];

    float sum = 0.0f;
    for (int jj = 0; jj < 64; jj++) {
        int sidx = r * 129 + half * 64 + jj;
        float e = expf(sc[sidx] - mx);
        sum += e;
        sc[sidx] = e;
    }
    sum += __shfl_xor_sync(0xffffffffu, sum, 1);
    float inv = 1.0f / sum;
    __syncthreads();  // V staged

    float acc[32];
    #pragma unroll
    for (int d = 0; d < 32; d++) acc[d] = 0.0f;

    for (int jj = 0; jj < 64; jj++) {
        float p = sc[r * 129 + half * 64 + jj];
        int j = half * 64 + jj;
        #pragma unroll
        for (int dd = 0; dd < 8; dd++) {
            float4 vv = kv4[j * 8 + dd];
            acc[dd * 4 + 0] = fmaf(p, vv.x, acc[dd * 4 + 0]);
            acc[dd * 4 + 1] = fmaf(p, vv.y, acc[dd * 4 + 1]);
            acc[dd * 4 + 2] = fmaf(p, vv.z, acc[dd * 4 + 2]);
            acc[dd * 4 + 3] = fmaf(p, vv.w, acc[dd * 4 + 3]);
        }
    }
    #pragma unroll
    for (int d = 0; d < 32; d++)
        acc[d] += __shfl_xor_sync(0xffffffffu, acc[d], 1);

    if (half == 0) {
        int obase = (b * 128 + r) * 256 + h * 32;
        #pragma unroll
        for (int d = 0; d < 32; d += 2) {
            float v0 = acc[d] * inv, v1 = acc[d + 1] * inv;
            bf16 h0, l0, h1, l1;
            split_bf16(v0, h0, l0);
            split_bf16(v1, h1, l1);
            __nv_bfloat162 H; H.x = h0; H.y = h1;
            __nv_bfloat162 L; L.x = l0; L.y = l1;
            *(__nv_bfloat162*)&g_aohi[obase + d] = H;
            *(__nv_bfloat162*)&g_aolo[obase + d] = L;
        }
    }
}

// ---------------- the persistent fused kernel --------------------------------
__global__ void __launch_bounds__(256)
k_fused(Params P)
{
    extern __shared__ char sm[];
    const int nC = gridDim.x;

    // Stage 1: fA (64 tiles) + fB (64) + mlp1 (256)
    for (int jid = blockIdx.x; jid < 384; jid += nC) {
        GJ J = {};
        if (jid < 128) {
            int q = jid & 63;
            J.Af = P.mw;
            J.Wf = (jid < 64) ? P.fcw : P.fcw + 65536;
            J.Cf = (jid < 64) ? g_fA : g_fB;
            J.rowBase = (q >> 2) * 64; J.colBase = (q & 3) * 64;
            J.aMode = 1; J.storeMode = 0;
        } else {
            int q = jid - 128;
            J.Af = P.x; J.Wf = P.w1; J.bias = P.b1;
            J.Chi = g_h1hi; J.Clo = g_h1lo;
            J.rowBase = (q >> 2) * 64; J.colBase = (q & 3) * 64;
            J.aMode = 0; J.act = 1; J.storeMode = 1;
        }
        gemmTile(J, sm);
    }
    gridBarrier(0, nC);

    // Stage 2: mlp2 (256) + conn (128)
    for (int jid = blockIdx.x; jid < 384; jid += nC) {
        if (jid < 256) {
            GJ J = {};
            J.Ahi = g_h1hi; J.Alo = g_h1lo;
            J.Wf = P.w2; J.bias = P.b2;
            J.Chi = g_xmhi; J.Clo = g_xmlo;
            J.rowBase = (jid >> 2) * 64; J.colBase = (jid & 3) * 64;
            J.aMode = 2; J.storeMode = 1;
            gemmTile(J, sm);
        } else {
            connJob(jid - 256, P, sm);
        }
    }
    gridBarrier(1, nC);

    // Stage 3: QKV (768)
    for (int jid = blockIdx.x; jid < 768; jid += nC) {
        int op = jid >> 8, q = jid & 255;
        GJ J = {};
        J.Ahi = g_xmhi; J.Alo = g_xmlo;
        J.Wf = (op == 0) ? P.wq : (op == 1) ? P.wk : P.wv;
        J.bias = (op == 0) ? P.bq : (op == 1) ? P.bk : P.bv;
        J.Cf = (op == 0) ? g_q : (op == 1) ? g_k : g_v;
        J.rowBase = (q >> 2) * 64; J.colBase = (q & 3) * 64;
        J.aMode = 2; J.storeMode = 2;
        gemmTile(J, sm);
    }
    gridBarrier(2, nC);

    // Stage 4: attention (256)
    for (int jid = blockIdx.x; jid < 256; jid += nC)
        attnJob(jid, sm);
    gridBarrier(3, nC);

    // Stage 5: output projection (256) -> d_out
    for (int jid = blockIdx.x; jid < 256; jid += nC) {
        GJ J = {};
        J.Ahi = g_aohi; J.Alo = g_aolo;
        J.Wf = P.ow; J.bias = P.ob; J.Cf = P.out;
        J.rowBase = (jid >> 2) * 64; J.colBase = (jid & 3) * 64;
        J.aMode = 2; J.storeMode = 0;
        gemmTile(J, sm);
    }
}

// ---------------- launch ------------------------------------------------------
extern "C" void kernel_launch(void* const* d_in, const int* in_sizes, int n_in,
                              void* d_out, int out_size)
{
    Params P;
    P.x    = (const float*)d_in[0];
    P.gu   = (const float*)d_in[1];
    P.mw   = (const float*)d_in[2];
    P.fcw  = (const float*)d_in[3];
    P.fcb  = (const float*)d_in[4];
    P.fccw = (const float*)d_in[5];
    P.fccb = (const float*)d_in[6];
    P.wq   = (const float*)d_in[7];
    P.bq   = (const float*)d_in[8];
    P.wk   = (const float*)d_in[9];
    P.bk   = (const float*)d_in[10];
    P.wv   = (const float*)d_in[11];
    P.bv   = (const float*)d_in[12];
    P.ow   = (const float*)d_in[13];
    P.ob   = (const float*)d_in[14];
    P.w1   = (const float*)d_in[15];
    P.b1   = (const float*)d_in[16];
    P.w2   = (const float*)d_in[17];
    P.b2   = (const float*)d_in[18];
    P.out  = (float*)d_out;

    static bool attrSet = false;
    if (!attrSet) {
        cudaFuncSetAttribute(k_fused, cudaFuncAttributeMaxDynamicSharedMemorySize, SMEM_TOTAL);
        attrSet = true;
    }
    k_fused<<<NCTA, 256, SMEM_TOTAL>>>(P);
}

// round 6
// speedup vs baseline: 1.4178x; 1.4178x over previous
#include <cuda_runtime.h>
#include <cuda_bf16.h>
#include <math.h>

// Problem constants: B=32, N=128, D=256, H=8, DK=32
typedef unsigned int u32;
typedef __nv_bfloat16 bf16;

// ---------------- scratch (static device globals; no allocation) -------------
__device__ __align__(16) float g_fA[1024 * 256];
__device__ __align__(16) float g_fB[1024 * 256];
__device__ __align__(16) float g_conn[8 * 128 * 128];
__device__ __align__(16) bf16 g_h1hi[4096 * 256];
__device__ __align__(16) bf16 g_h1lo[4096 * 256];
__device__ __align__(16) bf16 g_xmhi[4096 * 256];
__device__ __align__(16) bf16 g_xmlo[4096 * 256];
__device__ __align__(16) bf16 g_aohi[4096 * 256];
__device__ __align__(16) bf16 g_aolo[4096 * 256];

__device__ __forceinline__ float gelu_tanh(float x) {
    float x3 = x * x * x;
    float t = tanhf(0.7978845608028654f * (x + 0.044715f * x3));
    return 0.5f * x * (1.0f + t);
}

__device__ __forceinline__ void split_bf16(float v, bf16& h, bf16& l) {
    h = __float2bfloat16_rn(v);
    l = __float2bfloat16_rn(v - __bfloat162float(h));
}

__device__ __forceinline__ void cvt4(float4 v, uint2& hi, uint2& lo) {
    bf16 h0, l0, h1, l1, h2, l2, h3, l3;
    split_bf16(v.x, h0, l0); split_bf16(v.y, h1, l1);
    split_bf16(v.z, h2, l2); split_bf16(v.w, h3, l3);
    __nv_bfloat162 a, b, c, d;
    a.x = h0; a.y = h1; b.x = h2; b.y = h3;
    c.x = l0; c.y = l1; d.x = l2; d.y = l3;
    hi.x = *(u32*)&a; hi.y = *(u32*)&b;
    lo.x = *(u32*)&c; lo.y = *(u32*)&d;
}

#define LDSM4(r, addr)                                                        \
    asm volatile("ldmatrix.sync.aligned.m8n8.x4.shared.b16 {%0,%1,%2,%3}, [%4];" \
                 : "=r"(r[0]), "=r"(r[1]), "=r"(r[2]), "=r"(r[3]) : "r"(addr))

#define LDSM4T(r, addr)                                                       \
    asm volatile("ldmatrix.sync.aligned.m8n8.x4.trans.shared.b16 {%0,%1,%2,%3}, [%4];" \
                 : "=r"(r[0]), "=r"(r[1]), "=r"(r[2]), "=r"(r[3]) : "r"(addr))

#define MMA16816(d, a, b)                                                     \
    asm volatile("mma.sync.aligned.m16n8k16.row.col.f32.bf16.bf16.f32 "       \
                 "{%0,%1,%2,%3}, {%4,%5,%6,%7}, {%8,%9}, {%0,%1,%2,%3};"      \
                 : "+f"(d[0]), "+f"(d[1]), "+f"(d[2]), "+f"(d[3])             \
                 : "r"(a[0]), "r"(a[1]), "r"(a[2]), "r"(a[3]),                \
                   "r"(b[0]), "r"(b[1]))

// ---------------- GEMM-32: BM=32, BN=64, BK=32, 256 thr, 8 warps (2x4) -------
// Split-bf16 (3 MMAs). W always fp32, converted inline during staging.
struct Job {
    const float* Af;                 // fp32 A (aMode 0/1)
    const bf16 *Ahi, *Alo;           // bf16 planes (aMode 2)
    const float* Wf;                 // fp32 weight [256,256]
    const float* bias;
    float* Cf;
    bf16 *Chi, *Clo;
    int aMode;      // 0 fp32 row-major, 1 fp32 memory_w gather, 2 bf16 planes
    int act;        // gelu
    int storeMode;  // 0 fp32, 1 bf16 planes
};

struct ConnArgs {
    const float *fcb, *fccw, *fccb, *gu;
};

__device__ void connJob(int cid, ConnArgs CA, char* smemRaw);

__global__ void __launch_bounds__(256)
k_gemm32(Job j0, Job j1, Job j2, int n0, int n01, int n012, ConnArgs CA)
{
    __shared__ __align__(16) char smemRaw[28672];

    int jid = blockIdx.x;
    if (jid >= n012) { connJob(jid - n012, CA, smemRaw); return; }

    Job J; int tile;
    if (jid < n0)       { J = j0; tile = jid; }
    else if (jid < n01) { J = j1; tile = jid - n0; }
    else                { J = j2; tile = jid - n01; }

    bf16* sAhi = (bf16*)smemRaw;            // [2][32*40]
    bf16* sAlo = sAhi + 2 * 1280;
    bf16* sWhi = sAlo + 2 * 1280;           // [2][32*72]
    bf16* sWlo = sWhi + 2 * 2304;

    int rowBase = (tile >> 2) * 32;
    int colBase = (tile & 3) * 64;

    int t = threadIdx.x;
    int warp = t >> 5, lane = t & 31;
    int wm = warp >> 2, wn = warp & 3;
    int g = lane >> 3, r = lane & 7;

    u32 sAhiB = (u32)__cvta_generic_to_shared(sAhi);
    u32 sAloB = (u32)__cvta_generic_to_shared(sAlo);
    u32 sWhiB = (u32)__cvta_generic_to_shared(sWhi);
    u32 sWloB = (u32)__cvta_generic_to_shared(sWlo);

    // staging indices
    int pl = t >> 7, ps = t & 127;                 // planes: plane, 128 uint4
    int prow = ps >> 2, pseg = ps & 3;
    int arow = t >> 3, aseg = t & 7;               // fp32 A: 1 float4/thread
    int wrow0 = t >> 4, wseg0 = t & 15;            // W: 2 float4/thread
    int wrow1 = (t + 256) >> 4, wseg1 = (t + 256) & 15;

    uint4 pa;
    float4 fa, fw0, fw1;

    auto loadTile = [&](int kt) {
        if (J.aMode == 2) {
            const bf16* src = pl ? J.Alo : J.Ahi;
            pa = *(const uint4*)&src[(rowBase + prow) * 256 + kt + pseg * 8];
        } else if (J.aMode == 0) {
            fa = *(const float4*)&J.Af[(rowBase + arow) * 256 + kt + aseg * 4];
        } else {
            int rr = rowBase + arow;
            int h = rr >> 7, n = rr & 127;
            fa = *(const float4*)&J.Af[n * 2048 + h * 256 + kt + aseg * 4];
        }
        fw0 = *(const float4*)&J.Wf[(kt + wrow0) * 256 + colBase + wseg0 * 4];
        fw1 = *(const float4*)&J.Wf[(kt + wrow1) * 256 + colBase + wseg1 * 4];
    };

    auto storeTile = [&](int bb) {
        if (J.aMode == 2) {
            bf16* dst = pl ? sAlo : sAhi;
            *(uint4*)&dst[bb * 1280 + prow * 40 + pseg * 8] = pa;
        } else {
            uint2 hi, lo;
            cvt4(fa, hi, lo);
            *(uint2*)&sAhi[bb * 1280 + arow * 40 + aseg * 4] = hi;
            *(uint2*)&sAlo[bb * 1280 + arow * 40 + aseg * 4] = lo;
        }
        uint2 hi, lo;
        cvt4(fw0, hi, lo);
        *(uint2*)&sWhi[bb * 2304 + wrow0 * 72 + wseg0 * 4] = hi;
        *(uint2*)&sWlo[bb * 2304 + wrow0 * 72 + wseg0 * 4] = lo;
        cvt4(fw1, hi, lo);
        *(uint2*)&sWhi[bb * 2304 + wrow1 * 72 + wseg1 * 4] = hi;
        *(uint2*)&sWlo[bb * 2304 + wrow1 * 72 + wseg1 * 4] = lo;
    };

    float acc[2][4];
    #pragma unroll
    for (int nt = 0; nt < 2; nt++)
        #pragma unroll
        for (int i = 0; i < 4; i++) acc[nt][i] = 0.0f;

    loadTile(0);
    storeTile(0);
    __syncthreads();

    #pragma unroll
    for (int it = 0; it < 8; it++) {
        int bb = it & 1;
        if (it < 7) loadTile((it + 1) * 32);

        #pragma unroll
        for (int ks = 0; ks < 32; ks += 16) {
            u32 ah[4], al[4], bh[4], bl[4];
            {
                int rowA = wm * 16 + r + ((g & 1) << 3);
                int kcol = ks + ((g >> 1) << 3);
                u32 off = (u32)(bb * 1280 + rowA * 40 + kcol) * 2;
                LDSM4(ah, sAhiB + off);
                LDSM4(al, sAloB + off);
            }
            {
                int krow = ks + r + ((g & 1) << 3);
                int ncol = wn * 16 + ((g >> 1) << 3);
                u32 off = (u32)(bb * 2304 + krow * 72 + ncol) * 2;
                LDSM4T(bh, sWhiB + off);
                LDSM4T(bl, sWloB + off);
            }
            #pragma unroll
            for (int nt = 0; nt < 2; nt++) {
                MMA16816(acc[nt], ah, (&bh[nt * 2]));
                MMA16816(acc[nt], ah, (&bl[nt * 2]));
                MMA16816(acc[nt], al, (&bh[nt * 2]));
            }
        }
        __syncthreads();
        if (it < 7) {
            storeTile(1 - bb);
            __syncthreads();
        }
    }

    // epilogue
    #pragma unroll
    for (int nt = 0; nt < 2; nt++) {
        int row0 = rowBase + wm * 16 + (lane >> 2);
        int col0 = colBase + wn * 16 + nt * 8 + (lane & 3) * 2;
        float bv0 = J.bias ? J.bias[col0] : 0.0f;
        float bv1 = J.bias ? J.bias[col0 + 1] : 0.0f;
        #pragma unroll
        for (int half = 0; half < 2; half++) {
            int row = row0 + half * 8;
            float v0 = acc[nt][half * 2 + 0] + bv0;
            float v1 = acc[nt][half * 2 + 1] + bv1;
            if (J.act) { v0 = gelu_tanh(v0); v1 = gelu_tanh(v1); }
            if (J.storeMode == 0) {
                *(float2*)&J.Cf[row * 256 + col0] = make_float2(v0, v1);
            } else {
                bf16 h0, l0, h1, l1;
                split_bf16(v0, h0, l0);
                split_bf16(v1, h1, l1);
                __nv_bfloat162 H; H.x = h0; H.y = h1;
                __nv_bfloat162 L; L.x = l0; L.y = l1;
                *(__nv_bfloat162*)&J.Chi[row * 256 + col0] = H;
                *(__nv_bfloat162*)&J.Clo[row * 256 + col0] = L;
            }
        }
    }
}

// ---------------- conn job: 32i x 32j, 256 threads ---------------------------
__device__ void connJob(int cid, ConnArgs CA, char* smemRaw)
{
    float (*Aj)[33] = (float(*)[33])smemRaw;
    float (*Bi)[33] = (float(*)[33])(smemRaw + 32 * 33 * 4);
    float* Cs0 = (float*)(smemRaw + 2 * 32 * 33 * 4);
    float* Cs1 = Cs0 + 256;

    int h = cid >> 4;
    int ibase = ((cid >> 2) & 3) * 32;
    int jbase = (cid & 3) * 32;
    int t = threadIdx.x;
    int tx = t & 15, ty = t >> 4;

    Cs0[t] = CA.fccw[2 * t];
    Cs1[t] = CA.fccw[2 * t + 1];

    float l0[2][2] = {{0.f, 0.f}, {0.f, 0.f}};
    float l1[2][2] = {{0.f, 0.f}, {0.f, 0.f}};

    for (int d0 = 0; d0 < 256; d0 += 32) {
        if (d0) __syncthreads();
        int jr = t >> 3, c = (t & 7) * 4;
        float4 va = *(const float4*)&g_fA[(h * 128 + jbase + jr) * 256 + d0 + c];
        Aj[jr][c] = va.x; Aj[jr][c + 1] = va.y; Aj[jr][c + 2] = va.z; Aj[jr][c + 3] = va.w;
        float4 vb = *(const float4*)&g_fB[(h * 128 + ibase + jr) * 256 + d0 + c];
        float4 o = *(const float4*)&CA.fcb[d0 + c];
        Bi[jr][c] = vb.x + o.x; Bi[jr][c + 1] = vb.y + o.y;
        Bi[jr][c + 2] = vb.z + o.z; Bi[jr][c + 3] = vb.w + o.w;
        __syncthreads();

        #pragma unroll
        for (int dd = 0; dd < 32; dd++) {
            float a0 = Aj[tx * 2][dd], a1 = Aj[tx * 2 + 1][dd];
            float b0 = Bi[ty * 2][dd], b1 = Bi[ty * 2 + 1][dd];
            float c0v = Cs0[d0 + dd], c1v = Cs1[d0 + dd];
            float r00 = fmaxf(a0 + b0, 0.f), r10 = fmaxf(a1 + b0, 0.f);
            float r01 = fmaxf(a0 + b1, 0.f), r11 = fmaxf(a1 + b1, 0.f);
            l0[0][0] = fmaf(r00, c0v, l0[0][0]); l1[0][0] = fmaf(r00, c1v, l1[0][0]);
            l0[0][1] = fmaf(r10, c0v, l0[0][1]); l1[0][1] = fmaf(r10, c1v, l1[0][1]);
            l0[1][0] = fmaf(r01, c0v, l0[1][0]); l1[1][0] = fmaf(r01, c1v, l1[1][0]);
            l0[1][1] = fmaf(r11, c0v, l0[1][1]); l1[1][1] = fmaf(r11, c1v, l1[1][1]);
        }
    }

    float cb0 = CA.fccb[0], cb1 = CA.fccb[1];
    #pragma unroll
    for (int ii = 0; ii < 2; ii++) {
        int i = ibase + ty * 2 + ii;
        #pragma unroll
        for (int jj = 0; jj < 2; jj++) {
            int j = jbase + tx * 2 + jj;
            int idx = (h * 128 + i) * 128 + j;
            float2 u2 = *(const float2*)&CA.gu[idx * 2];
            float gg0 = -logf(-logf(u2.x + 1e-10f) + 1e-10f);
            float gg1 = -logf(-logf(u2.y + 1e-10f) + 1e-10f);
            g_conn[idx] = ((l1[ii][jj] + cb1 + gg1) > (l0[ii][jj] + cb0 + gg0)) ? 1.0f : 0.0f;
        }
    }
}

// ---------------- fused QKV + attention: one CTA per (b,h), 256 threads ------
// GEMM: xm[b] (128x256, planes) @ [wq|wk|wv] head-h cols (256x96) -> smem Q,K,V
// then masked attention fully in smem; output -> ao planes.
// smem: staging (67584 B, overlaid by sc 66048 B) + Q/K/V (55296) + cmask (2048)
#define QKV_SMEM (67584 + 55296 + 2048)

__global__ void __launch_bounds__(256)
k_qkv_attn(const float* __restrict__ wq, const float* __restrict__ bq,
           const float* __restrict__ wk, const float* __restrict__ bk,
           const float* __restrict__ wv, const float* __restrict__ bv)
{
    extern __shared__ char sm[];
    bf16* sAhi = (bf16*)sm;                  // [2][128*40]  (20480 B)
    bf16* sAlo = sAhi + 2 * 5120;            // (20480 B)
    bf16* sWhi = sAlo + 2 * 5120;            // [2][32*104]  (13312 B)
    bf16* sWlo = sWhi + 2 * 3328;            // (13312 B) -> end 67584
    float* sc  = (float*)sm;                 // overlay: 128*129 floats
    float* sQ  = (float*)(sm + 67584);       // [128][36]
    float* sK  = sQ + 128 * 36;
    float* sV  = sK + 128 * 36;
    u32* cmask = (u32*)(sm + 67584 + 55296);

    int bid = blockIdx.x;
    int b = bid >> 3, h = bid & 7;
    int t = threadIdx.x;
    int warp = t >> 5, lane = t & 31;
    int g = lane >> 3, r = lane & 7;
    int gRow = b * 128;

    u32 sAhiB = (u32)__cvta_generic_to_shared(sAhi);
    u32 sAloB = (u32)__cvta_generic_to_shared(sAlo);
    u32 sWhiB = (u32)__cvta_generic_to_shared(sWhi);
    u32 sWloB = (u32)__cvta_generic_to_shared(sWlo);

    // build conn bitmask first (independent of GEMM)
    {
        const float* cr = g_conn + h * 16384;
        for (int i0b = 0; i0b < 128; i0b += 2) {
            int i0 = i0b + (warp >> 2);
            float c = cr[i0 * 128 + (warp & 3) * 32 + lane];
            u32 bal = __ballot_sync(0xffffffffu, c > 0.5f);
            if (lane == 0) cmask[i0 * 4 + (warp & 3)] = bal;
        }
    }

    // ---- GEMM phase: 128x96, k=256 ----
    int wrow = t >> 3, wseg = t & 7;   // W per z: 32 rows x 8 segs x 4 cols
    uint4 pah[2], pal[2];
    float4 fwq, fwk, fwv;

    auto loadTile = [&](int kt) {
        #pragma unroll
        for (int u = 0; u < 2; u++) {
            int s = t * 2 + u;
            int row = s >> 2, seg = s & 3;
            pah[u] = *(const uint4*)&g_xmhi[(gRow + row) * 256 + kt + seg * 8];
            pal[u] = *(const uint4*)&g_xmlo[(gRow + row) * 256 + kt + seg * 8];
        }
        int gk = (kt + wrow) * 256 + h * 32 + wseg * 4;
        fwq = *(const float4*)&wq[gk];
        fwk = *(const float4*)&wk[gk];
        fwv = *(const float4*)&wv[gk];
    };

    auto storeTile = [&](int bb) {
        #pragma unroll
        for (int u = 0; u < 2; u++) {
            int s = t * 2 + u;
            int row = s >> 2, seg = s & 3;
            *(uint4*)&sAhi[bb * 5120 + row * 40 + seg * 8] = pah[u];
            *(uint4*)&sAlo[bb * 5120 + row * 40 + seg * 8] = pal[u];
        }
        uint2 hi, lo;
        int base = bb * 3328 + wrow * 104 + wseg * 4;
        cvt4(fwq, hi, lo);
        *(uint2*)&sWhi[base] = hi;      *(uint2*)&sWlo[base] = lo;
        cvt4(fwk, hi, lo);
        *(uint2*)&sWhi[base + 32] = hi; *(uint2*)&sWlo[base + 32] = lo;
        cvt4(fwv, hi, lo);
        *(uint2*)&sWhi[base + 64] = hi; *(uint2*)&sWlo[base + 64] = lo;
    };

    float acc[12][4];
    #pragma unroll
    for (int j = 0; j < 12; j++)
        #pragma unroll
        for (int i = 0; i < 4; i++) acc[j][i] = 0.0f;

    loadTile(0);
    storeTile(0);
    __syncthreads();

    #pragma unroll
    for (int it = 0; it < 8; it++) {
        int bb = it & 1;
        if (it < 7) loadTile((it + 1) * 32);

        #pragma unroll
        for (int ks = 0; ks < 32; ks += 16) {
            u32 ah[4], al[4];
            {
                int rowA = warp * 16 + r + ((g & 1) << 3);
                int kcol = ks + ((g >> 1) << 3);
                u32 off = (u32)(bb * 5120 + rowA * 40 + kcol) * 2;
                LDSM4(ah, sAhiB + off);
                LDSM4(al, sAloB + off);
            }
            #pragma unroll
            for (int n16 = 0; n16 < 6; n16++) {
                u32 bh[4], bl[4];
                int krow = ks + r + ((g & 1) << 3);
                int ncol = n16 * 16 + ((g >> 1) << 3);
                u32 off = (u32)(bb * 3328 + krow * 104 + ncol) * 2;
                LDSM4T(bh, sWhiB + off);
                LDSM4T(bl, sWloB + off);
                MMA16816(acc[n16 * 2], ah, (&bh[0]));
                MMA16816(acc[n16 * 2], ah, (&bl[0]));
                MMA16816(acc[n16 * 2], al, (&bh[0]));
                MMA16816(acc[n16 * 2 + 1], ah, (&bh[2]));
                MMA16816(acc[n16 * 2 + 1], ah, (&bl[2]));
                MMA16816(acc[n16 * 2 + 1], al, (&bh[2]));
            }
        }
        __syncthreads();
        if (it < 7) {
            storeTile(1 - bb);
            __syncthreads();
        }
    }

    // epilogue: bias + write Q/K/V to smem
    #pragma unroll
    for (int j = 0; j < 12; j++) {
        int colg = j * 8 + (lane & 3) * 2;
        int z = colg >> 5, c = colg & 31;
        const float* bz = (z == 0) ? bq : (z == 1) ? bk : bv;
        float* sZ = (z == 0) ? sQ : (z == 1) ? sK : sV;
        float b0 = bz[h * 32 + c], b1 = bz[h * 32 + c + 1];
        #pragma unroll
        for (int half = 0; half < 2; half++) {
            int row = warp * 16 + (lane >> 2) + half * 8;
            *(float2*)&sZ[row * 36 + c] =
                make_float2(acc[j][half * 2] + b0, acc[j][half * 2 + 1] + b1);
        }
    }
    __syncthreads();   // Q/K/V ready; staging dead -> sc may be written

    // ---- attention phase ----
    int rw = t >> 1, half = t & 1;
    float4 qr[8];
    const float4* qp = (const float4*)(sQ + rw * 36);
    #pragma unroll
    for (int d = 0; d < 8; d++) qr[d] = qp[d];
    u32 m0 = cmask[rw * 4 + half * 2], m1 = cmask[rw * 4 + half * 2 + 1];

    const float scale = 0.17677669529663687f;  // 1/sqrt(32)
    float mx = -INFINITY;

    #pragma unroll
    for (int w2 = 0; w2 < 2; w2++) {
        u32 word = w2 ? m1 : m0;
        for (int jj = 0; jj < 32; jj++) {
            int j = half * 64 + w2 * 32 + jj;
            float s;
            if ((word >> jj) & 1u) {
                const float4* kr = (const float4*)(sK + j * 36);
                float a0 = 0.f, a1 = 0.f, a2 = 0.f, a3 = 0.f;
                #pragma unroll
                for (int d = 0; d < 8; d++) {
                    float4 kk4 = kr[d];
                    a0 = fmaf(qr[d].x, kk4.x, a0);
                    a1 = fmaf(qr[d].y, kk4.y, a1);
                    a2 = fmaf(qr[d].z, kk4.z, a2);
                    a3 = fmaf(qr[d].w, kk4.w, a3);
                }
                s = ((a0 + a1) + (a2 + a3)) * scale;
                mx = fmaxf(mx, s);
            } else {
                s = -INFINITY;
            }
            sc[rw * 129 + j] = s;
        }
    }
    mx = fmaxf(mx, __shfl_xor_sync(0xffffffffu, mx, 1));

    float sum = 0.0f;
    for (int jj = 0; jj < 64; jj++) {
        int sidx = rw * 129 + half * 64 + jj;
        float e = expf(sc[sidx] - mx);
        sum += e;
        sc[sidx] = e;
    }
    sum += __shfl_xor_sync(0xffffffffu, sum, 1);
    float inv = 1.0f / sum;

    float acco[32];
    #pragma unroll
    for (int d = 0; d < 32; d++) acco[d] = 0.0f;

    for (int jj = 0; jj < 64; jj++) {
        int j = half * 64 + jj;
        float p = sc[rw * 129 + j];
        const float4* vr = (const float4*)(sV + j * 36);
        #pragma unroll
        for (int dd = 0; dd < 8; dd++) {
            float4 vv = vr[dd];
            acco[dd * 4 + 0] = fmaf(p, vv.x, acco[dd * 4 + 0]);
            acco[dd * 4 + 1] = fmaf(p, vv.y, acco[dd * 4 + 1]);
            acco[dd * 4 + 2] = fmaf(p, vv.z, acco[dd * 4 + 2]);
            acco[dd * 4 + 3] = fmaf(p, vv.w, acco[dd * 4 + 3]);
        }
    }
    #pragma unroll
    for (int d = 0; d < 32; d++)
        acco[d] += __shfl_xor_sync(0xffffffffu, acco[d], 1);

    if (half == 0) {
        int obase = (b * 128 + rw) * 256 + h * 32;
        #pragma unroll
        for (int d = 0; d < 32; d += 2) {
            float v0 = acco[d] * inv, v1 = acco[d + 1] * inv;
            bf16 h0, l0, h1, l1;
            split_bf16(v0, h0, l0);
            split_bf16(v1, h1, l1);
            __nv_bfloat162 H; H.x = h0; H.y = h1;
            __nv_bfloat162 L; L.x = l0; L.y = l1;
            *(__nv_bfloat162*)&g_aohi[obase + d] = H;
            *(__nv_bfloat162*)&g_aolo[obase + d] = L;
        }
    }
}

// ---------------- launch ------------------------------------------------------
extern "C" void kernel_launch(void* const* d_in, const int* in_sizes, int n_in,
                              void* d_out, int out_size)
{
    const float* x        = (const float*)d_in[0];
    const float* gumbel_u = (const float*)d_in[1];
    const float* memory_w = (const float*)d_in[2];
    const float* fc_out_w = (const float*)d_in[3];
    const float* fc_out_b = (const float*)d_in[4];
    const float* fc_cat_w = (const float*)d_in[5];
    const float* fc_cat_b = (const float*)d_in[6];
    const float* wq       = (const float*)d_in[7];
    const float* bq       = (const float*)d_in[8];
    const float* wk       = (const float*)d_in[9];
    const float* bk       = (const float*)d_in[10];
    const float* wv       = (const float*)d_in[11];
    const float* bv       = (const float*)d_in[12];
    const float* out_w    = (const float*)d_in[13];
    const float* out_b    = (const float*)d_in[14];
    const float* mlp_w1   = (const float*)d_in[15];
    const float* mlp_b1   = (const float*)d_in[16];
    const float* mlp_w2   = (const float*)d_in[17];
    const float* mlp_b2   = (const float*)d_in[18];

    float *fA, *fB;
    cudaGetSymbolAddress((void**)&fA, g_fA);
    cudaGetSymbolAddress((void**)&fB, g_fB);
    bf16 *h1hi, *h1lo, *xmhi, *xmlo, *aohi, *aolo;
    cudaGetSymbolAddress((void**)&h1hi, g_h1hi);
    cudaGetSymbolAddress((void**)&h1lo, g_h1lo);
    cudaGetSymbolAddress((void**)&xmhi, g_xmhi);
    cudaGetSymbolAddress((void**)&xmlo, g_xmlo);
    cudaGetSymbolAddress((void**)&aohi, g_aohi);
    cudaGetSymbolAddress((void**)&aolo, g_aolo);

    static bool attrSet = false;
    if (!attrSet) {
        cudaFuncSetAttribute(k_qkv_attn, cudaFuncAttributeMaxDynamicSharedMemorySize, QKV_SMEM);
        attrSet = true;
    }

    Job JZ = {};
    ConnArgs CA = { fc_out_b, fc_cat_w, fc_cat_b, gumbel_u };

    // L1: fA (128 tiles) + fB (128) + mlp1 (512)
    {
        Job ja = JZ, jb = JZ, jm = JZ;
        ja.Af = memory_w; ja.Wf = fc_out_w;         ja.Cf = fA; ja.aMode = 1;
        jb.Af = memory_w; jb.Wf = fc_out_w + 65536; jb.Cf = fB; jb.aMode = 1;
        jm.Af = x; jm.Wf = mlp_w1; jm.bias = mlp_b1;
        jm.Chi = h1hi; jm.Clo = h1lo; jm.aMode = 0; jm.act = 1; jm.storeMode = 1;
        k_gemm32<<<768, 256>>>(ja, jb, jm, 128, 256, 768, CA);
    }

    // L2: mlp2 (512 tiles) + conn (128 jobs)
    {
        Job j = JZ;
        j.Ahi = h1hi; j.Alo = h1lo; j.Wf = mlp_w2; j.bias = mlp_b2;
        j.Chi = xmhi; j.Clo = xmlo; j.aMode = 2; j.storeMode = 1;
        k_gemm32<<<640, 256>>>(j, JZ, JZ, 512, 512, 512, CA);
    }

    // L3: fused QKV + attention (256 CTAs, one per (b,h))
    k_qkv_attn<<<256, 256, QKV_SMEM>>>(wq, bq, wk, bk, wv, bv);

    // L4: output projection -> d_out
    {
        Job j = JZ;
        j.Ahi = aohi; j.Alo = aolo; j.Wf = out_w; j.bias = out_b;
        j.Cf = (float*)d_out; j.aMode = 2; j.storeMode = 0;
        k_gemm32<<<512, 256>>>(j, JZ, JZ, 512, 512, 512, CA);
    }
}

// round 7
// speedup vs baseline: 1.8645x; 1.3151x over previous
#include <cuda_runtime.h>
#include <cuda_bf16.h>
#include <math.h>

// Problem constants: B=32, N=128, D=256, H=8, DK=32
typedef unsigned int u32;
typedef __nv_bfloat16 bf16;

// ---------------- scratch (static device globals; no allocation) -------------
__device__ __align__(16) float g_fA[1024 * 256];
__device__ __align__(16) float g_fB[1024 * 256];
__device__ __align__(16) float g_conn[8 * 128 * 128];
__device__ __align__(16) bf16 g_h1hi[4096 * 256];
__device__ __align__(16) bf16 g_h1lo[4096 * 256];
__device__ __align__(16) bf16 g_xmhi[4096 * 256];
__device__ __align__(16) bf16 g_xmlo[4096 * 256];
__device__ __align__(16) bf16 g_aohi[4096 * 256];
__device__ __align__(16) bf16 g_aolo[4096 * 256];

__device__ __forceinline__ float gelu_tanh(float x) {
    float x3 = x * x * x;
    float t = tanhf(0.7978845608028654f * (x + 0.044715f * x3));
    return 0.5f * x * (1.0f + t);
}

__device__ __forceinline__ void split_bf16(float v, bf16& h, bf16& l) {
    h = __float2bfloat16_rn(v);
    l = __float2bfloat16_rn(v - __bfloat162float(h));
}

__device__ __forceinline__ void cvt4(float4 v, uint2& hi, uint2& lo) {
    bf16 h0, l0, h1, l1, h2, l2, h3, l3;
    split_bf16(v.x, h0, l0); split_bf16(v.y, h1, l1);
    split_bf16(v.z, h2, l2); split_bf16(v.w, h3, l3);
    __nv_bfloat162 a, b, c, d;
    a.x = h0; a.y = h1; b.x = h2; b.y = h3;
    c.x = l0; c.y = l1; d.x = l2; d.y = l3;
    hi.x = *(u32*)&a; hi.y = *(u32*)&b;
    lo.x = *(u32*)&c; lo.y = *(u32*)&d;
}

__device__ __forceinline__ void packP(float x, float y, u32& hi, u32& lo) {
    bf16 hx, lx, hy, ly;
    split_bf16(x, hx, lx);
    split_bf16(y, hy, ly);
    __nv_bfloat162 H; H.x = hx; H.y = hy;
    __nv_bfloat162 L; L.x = lx; L.y = ly;
    hi = *(u32*)&H; lo = *(u32*)&L;
}

#define LDSM4(r, addr)                                                        \
    asm volatile("ldmatrix.sync.aligned.m8n8.x4.shared.b16 {%0,%1,%2,%3}, [%4];" \
                 : "=r"(r[0]), "=r"(r[1]), "=r"(r[2]), "=r"(r[3]) : "r"(addr))

#define LDSM4T(r, addr)                                                       \
    asm volatile("ldmatrix.sync.aligned.m8n8.x4.trans.shared.b16 {%0,%1,%2,%3}, [%4];" \
                 : "=r"(r[0]), "=r"(r[1]), "=r"(r[2]), "=r"(r[3]) : "r"(addr))

#define MMA16816(d, a, b)                                                     \
    asm volatile("mma.sync.aligned.m16n8k16.row.col.f32.bf16.bf16.f32 "       \
                 "{%0,%1,%2,%3}, {%4,%5,%6,%7}, {%8,%9}, {%0,%1,%2,%3};"      \
                 : "+f"(d[0]), "+f"(d[1]), "+f"(d[2]), "+f"(d[3])             \
                 : "r"(a[0]), "r"(a[1]), "r"(a[2]), "r"(a[3]),                \
                   "r"(b[0]), "r"(b[1]))

// ---------------- GEMM-32: BM=32, BN=64, BK=32, 256 thr, 8 warps (2x4) -------
struct Job {
    const float* Af;
    const bf16 *Ahi, *Alo;
    const float* Wf;
    const float* bias;
    float* Cf;
    bf16 *Chi, *Clo;
    int aMode;      // 0 fp32 row-major, 1 fp32 memory_w gather, 2 bf16 planes
    int act;
    int storeMode;  // 0 fp32, 1 bf16 planes
};

struct ConnArgs {
    const float *fcb, *fccw, *fccb, *gu;
};

__device__ void connJob(int cid, ConnArgs CA, char* smemRaw);

__global__ void __launch_bounds__(256)
k_gemm32(Job j0, Job j1, Job j2, int n0, int n01, int n012, ConnArgs CA)
{
    __shared__ __align__(16) char smemRaw[28672];

    int jid = blockIdx.x;
    if (jid >= n012) { connJob(jid - n012, CA, smemRaw); return; }

    Job J; int tile;
    if (jid < n0)       { J = j0; tile = jid; }
    else if (jid < n01) { J = j1; tile = jid - n0; }
    else                { J = j2; tile = jid - n01; }

    bf16* sAhi = (bf16*)smemRaw;            // [2][32*40]
    bf16* sAlo = sAhi + 2 * 1280;
    bf16* sWhi = sAlo + 2 * 1280;           // [2][32*72]
    bf16* sWlo = sWhi + 2 * 2304;

    int rowBase = (tile >> 2) * 32;
    int colBase = (tile & 3) * 64;

    int t = threadIdx.x;
    int warp = t >> 5, lane = t & 31;
    int wm = warp >> 2, wn = warp & 3;
    int g = lane >> 3, r = lane & 7;

    u32 sAhiB = (u32)__cvta_generic_to_shared(sAhi);
    u32 sAloB = (u32)__cvta_generic_to_shared(sAlo);
    u32 sWhiB = (u32)__cvta_generic_to_shared(sWhi);
    u32 sWloB = (u32)__cvta_generic_to_shared(sWlo);

    int pl = t >> 7, ps = t & 127;
    int prow = ps >> 2, pseg = ps & 3;
    int arow = t >> 3, aseg = t & 7;
    int wrow0 = t >> 4, wseg0 = t & 15;
    int wrow1 = (t + 256) >> 4, wseg1 = (t + 256) & 15;

    uint4 pa;
    float4 fa, fw0, fw1;

    auto loadTile = [&](int kt) {
        if (J.aMode == 2) {
            const bf16* src = pl ? J.Alo : J.Ahi;
            pa = *(const uint4*)&src[(rowBase + prow) * 256 + kt + pseg * 8];
        } else if (J.aMode == 0) {
            fa = *(const float4*)&J.Af[(rowBase + arow) * 256 + kt + aseg * 4];
        } else {
            int rr = rowBase + arow;
            int h = rr >> 7, n = rr & 127;
            fa = *(const float4*)&J.Af[n * 2048 + h * 256 + kt + aseg * 4];
        }
        fw0 = *(const float4*)&J.Wf[(kt + wrow0) * 256 + colBase + wseg0 * 4];
        fw1 = *(const float4*)&J.Wf[(kt + wrow1) * 256 + colBase + wseg1 * 4];
    };

    auto storeTile = [&](int bb) {
        if (J.aMode == 2) {
            bf16* dst = pl ? sAlo : sAhi;
            *(uint4*)&dst[bb * 1280 + prow * 40 + pseg * 8] = pa;
        } else {
            uint2 hi, lo;
            cvt4(fa, hi, lo);
            *(uint2*)&sAhi[bb * 1280 + arow * 40 + aseg * 4] = hi;
            *(uint2*)&sAlo[bb * 1280 + arow * 40 + aseg * 4] = lo;
        }
        uint2 hi, lo;
        cvt4(fw0, hi, lo);
        *(uint2*)&sWhi[bb * 2304 + wrow0 * 72 + wseg0 * 4] = hi;
        *(uint2*)&sWlo[bb * 2304 + wrow0 * 72 + wseg0 * 4] = lo;
        cvt4(fw1, hi, lo);
        *(uint2*)&sWhi[bb * 2304 + wrow1 * 72 + wseg1 * 4] = hi;
        *(uint2*)&sWlo[bb * 2304 + wrow1 * 72 + wseg1 * 4] = lo;
    };

    float acc[2][4];
    #pragma unroll
    for (int nt = 0; nt < 2; nt++)
        #pragma unroll
        for (int i = 0; i < 4; i++) acc[nt][i] = 0.0f;

    loadTile(0);
    storeTile(0);
    __syncthreads();

    #pragma unroll
    for (int it = 0; it < 8; it++) {
        int bb = it & 1;
        if (it < 7) loadTile((it + 1) * 32);

        #pragma unroll
        for (int ks = 0; ks < 32; ks += 16) {
            u32 ah[4], al[4], bh[4], bl[4];
            {
                int rowA = wm * 16 + r + ((g & 1) << 3);
                int kcol = ks + ((g >> 1) << 3);
                u32 off = (u32)(bb * 1280 + rowA * 40 + kcol) * 2;
                LDSM4(ah, sAhiB + off);
                LDSM4(al, sAloB + off);
            }
            {
                int krow = ks + r + ((g & 1) << 3);
                int ncol = wn * 16 + ((g >> 1) << 3);
                u32 off = (u32)(bb * 2304 + krow * 72 + ncol) * 2;
                LDSM4T(bh, sWhiB + off);
                LDSM4T(bl, sWloB + off);
            }
            #pragma unroll
            for (int nt = 0; nt < 2; nt++) {
                MMA16816(acc[nt], ah, (&bh[nt * 2]));
                MMA16816(acc[nt], ah, (&bl[nt * 2]));
                MMA16816(acc[nt], al, (&bh[nt * 2]));
            }
        }
        __syncthreads();
        if (it < 7) {
            storeTile(1 - bb);
            __syncthreads();
        }
    }

    #pragma unroll
    for (int nt = 0; nt < 2; nt++) {
        int row0 = rowBase + wm * 16 + (lane >> 2);
        int col0 = colBase + wn * 16 + nt * 8 + (lane & 3) * 2;
        float bv0 = J.bias ? J.bias[col0] : 0.0f;
        float bv1 = J.bias ? J.bias[col0 + 1] : 0.0f;
        #pragma unroll
        for (int half = 0; half < 2; half++) {
            int row = row0 + half * 8;
            float v0 = acc[nt][half * 2 + 0] + bv0;
            float v1 = acc[nt][half * 2 + 1] + bv1;
            if (J.act) { v0 = gelu_tanh(v0); v1 = gelu_tanh(v1); }
            if (J.storeMode == 0) {
                *(float2*)&J.Cf[row * 256 + col0] = make_float2(v0, v1);
            } else {
                bf16 h0, l0, h1, l1;
                split_bf16(v0, h0, l0);
                split_bf16(v1, h1, l1);
                __nv_bfloat162 H; H.x = h0; H.y = h1;
                __nv_bfloat162 L; L.x = l0; L.y = l1;
                *(__nv_bfloat162*)&J.Chi[row * 256 + col0] = H;
                *(__nv_bfloat162*)&J.Clo[row * 256 + col0] = L;
            }
        }
    }
}

// ---------------- conn job: 32i x 32j, 256 threads ---------------------------
__device__ void connJob(int cid, ConnArgs CA, char* smemRaw)
{
    float (*Aj)[33] = (float(*)[33])smemRaw;
    float (*Bi)[33] = (float(*)[33])(smemRaw + 32 * 33 * 4);
    float* Cs0 = (float*)(smemRaw + 2 * 32 * 33 * 4);
    float* Cs1 = Cs0 + 256;

    int h = cid >> 4;
    int ibase = ((cid >> 2) & 3) * 32;
    int jbase = (cid & 3) * 32;
    int t = threadIdx.x;
    int tx = t & 15, ty = t >> 4;

    Cs0[t] = CA.fccw[2 * t];
    Cs1[t] = CA.fccw[2 * t + 1];

    float l0[2][2] = {{0.f, 0.f}, {0.f, 0.f}};
    float l1[2][2] = {{0.f, 0.f}, {0.f, 0.f}};

    for (int d0 = 0; d0 < 256; d0 += 32) {
        if (d0) __syncthreads();
        int jr = t >> 3, c = (t & 7) * 4;
        float4 va = *(const float4*)&g_fA[(h * 128 + jbase + jr) * 256 + d0 + c];
        Aj[jr][c] = va.x; Aj[jr][c + 1] = va.y; Aj[jr][c + 2] = va.z; Aj[jr][c + 3] = va.w;
        float4 vb = *(const float4*)&g_fB[(h * 128 + ibase + jr) * 256 + d0 + c];
        float4 o = *(const float4*)&CA.fcb[d0 + c];
        Bi[jr][c] = vb.x + o.x; Bi[jr][c + 1] = vb.y + o.y;
        Bi[jr][c + 2] = vb.z + o.z; Bi[jr][c + 3] = vb.w + o.w;
        __syncthreads();

        #pragma unroll
        for (int dd = 0; dd < 32; dd++) {
            float a0 = Aj[tx * 2][dd], a1 = Aj[tx * 2 + 1][dd];
            float b0 = Bi[ty * 2][dd], b1 = Bi[ty * 2 + 1][dd];
            float c0v = Cs0[d0 + dd], c1v = Cs1[d0 + dd];
            float r00 = fmaxf(a0 + b0, 0.f), r10 = fmaxf(a1 + b0, 0.f);
            float r01 = fmaxf(a0 + b1, 0.f), r11 = fmaxf(a1 + b1, 0.f);
            l0[0][0] = fmaf(r00, c0v, l0[0][0]); l1[0][0] = fmaf(r00, c1v, l1[0][0]);
            l0[0][1] = fmaf(r10, c0v, l0[0][1]); l1[0][1] = fmaf(r10, c1v, l1[0][1]);
            l0[1][0] = fmaf(r01, c0v, l0[1][0]); l1[1][0] = fmaf(r01, c1v, l1[1][0]);
            l0[1][1] = fmaf(r11, c0v, l0[1][1]); l1[1][1] = fmaf(r11, c1v, l1[1][1]);
        }
    }

    float cb0 = CA.fccb[0], cb1 = CA.fccb[1];
    #pragma unroll
    for (int ii = 0; ii < 2; ii++) {
        int i = ibase + ty * 2 + ii;
        #pragma unroll
        for (int jj = 0; jj < 2; jj++) {
            int j = jbase + tx * 2 + jj;
            int idx = (h * 128 + i) * 128 + j;
            float2 u2 = *(const float2*)&CA.gu[idx * 2];
            float gg0 = -logf(-logf(u2.x + 1e-10f) + 1e-10f);
            float gg1 = -logf(-logf(u2.y + 1e-10f) + 1e-10f);
            g_conn[idx] = ((l1[ii][jj] + cb1 + gg1) > (l0[ii][jj] + cb0 + gg0)) ? 1.0f : 0.0f;
        }
    }
}

// ---------------- fused QKV + tensor-core attention: one CTA per (b,h) -------
// Phase 1: Q/K/V = xm @ W heads (split-bf16 MMA) -> bf16 hi/lo planes in smem.
// Phase 2: S = QK^T (MMA, registers), mask, softmax, O = P V (MMA) -> ao planes.
// smem: staging 67584 B (overlaid post-GEMM by 6 planes of 128x40 bf16 = 61440)
//       + cmask 2048 at offset 67584.
#define QKV_SMEM (67584 + 2048)

__global__ void __launch_bounds__(256)
k_qkv_attn(const float* __restrict__ wq, const float* __restrict__ bq,
           const float* __restrict__ wk, const float* __restrict__ bk,
           const float* __restrict__ wv, const float* __restrict__ bv)
{
    extern __shared__ char sm[];
    // staging layout (GEMM phase)
    bf16* sAhi = (bf16*)sm;                  // [2][128*40]
    bf16* sAlo = sAhi + 2 * 5120;
    bf16* sWhi = sAlo + 2 * 5120;            // [2][32*104]
    bf16* sWlo = sWhi + 2 * 3328;
    // plane overlay (attention phase): 6 x [128*40] bf16
    bf16* sQhi = (bf16*)sm;
    bf16* sQlo = sQhi + 5120;
    bf16* sKhi = sQlo + 5120;
    bf16* sKlo = sKhi + 5120;
    bf16* sVhi = sKlo + 5120;
    bf16* sVlo = sVhi + 5120;
    u32* cmask = (u32*)(sm + 67584);

    int bid = blockIdx.x;
    int b = bid >> 3, h = bid & 7;
    int t = threadIdx.x;
    int warp = t >> 5, lane = t & 31;
    int g = lane >> 3, r = lane & 7;
    int gRow = b * 128;

    u32 smB = (u32)__cvta_generic_to_shared(sm);
    u32 sAhiB = smB, sAloB = smB + 20480, sWhiB = smB + 40960, sWloB = smB + 54272;
    u32 sQhiB = smB, sQloB = smB + 10240;
    u32 sKhiB = smB + 20480, sKloB = smB + 30720;
    u32 sVhiB = smB + 40960, sVloB = smB + 51200;

    // conn bitmask (separate smem region; safe during GEMM)
    {
        const float* cr = g_conn + h * 16384;
        for (int i0b = 0; i0b < 128; i0b += 2) {
            int i0 = i0b + (warp >> 2);
            float c = cr[i0 * 128 + (warp & 3) * 32 + lane];
            u32 bal = __ballot_sync(0xffffffffu, c > 0.5f);
            if (lane == 0) cmask[i0 * 4 + (warp & 3)] = bal;
        }
    }

    // ---- Phase 1: QKV GEMM 128x96, k=256 ----
    int wrow = t >> 3, wseg = t & 7;
    uint4 pah[2], pal[2];
    float4 fwq, fwk, fwv;

    auto loadTile = [&](int kt) {
        #pragma unroll
        for (int u = 0; u < 2; u++) {
            int s = t * 2 + u;
            int row = s >> 2, seg = s & 3;
            pah[u] = *(const uint4*)&g_xmhi[(gRow + row) * 256 + kt + seg * 8];
            pal[u] = *(const uint4*)&g_xmlo[(gRow + row) * 256 + kt + seg * 8];
        }
        int gk = (kt + wrow) * 256 + h * 32 + wseg * 4;
        fwq = *(const float4*)&wq[gk];
        fwk = *(const float4*)&wk[gk];
        fwv = *(const float4*)&wv[gk];
    };

    auto storeTile = [&](int bb) {
        #pragma unroll
        for (int u = 0; u < 2; u++) {
            int s = t * 2 + u;
            int row = s >> 2, seg = s & 3;
            *(uint4*)&sAhi[bb * 5120 + row * 40 + seg * 8] = pah[u];
            *(uint4*)&sAlo[bb * 5120 + row * 40 + seg * 8] = pal[u];
        }
        uint2 hi, lo;
        int base = bb * 3328 + wrow * 104 + wseg * 4;
        cvt4(fwq, hi, lo);
        *(uint2*)&sWhi[base] = hi;      *(uint2*)&sWlo[base] = lo;
        cvt4(fwk, hi, lo);
        *(uint2*)&sWhi[base + 32] = hi; *(uint2*)&sWlo[base + 32] = lo;
        cvt4(fwv, hi, lo);
        *(uint2*)&sWhi[base + 64] = hi; *(uint2*)&sWlo[base + 64] = lo;
    };

    float acc[12][4];
    #pragma unroll
    for (int j = 0; j < 12; j++)
        #pragma unroll
        for (int i = 0; i < 4; i++) acc[j][i] = 0.0f;

    loadTile(0);
    storeTile(0);
    __syncthreads();

    #pragma unroll
    for (int it = 0; it < 8; it++) {
        int bb = it & 1;
        if (it < 7) loadTile((it + 1) * 32);

        #pragma unroll
        for (int ks = 0; ks < 32; ks += 16) {
            u32 ah[4], al[4];
            {
                int rowA = warp * 16 + r + ((g & 1) << 3);
                int kcol = ks + ((g >> 1) << 3);
                u32 off = (u32)(bb * 5120 + rowA * 40 + kcol) * 2;
                LDSM4(ah, sAhiB + off);
                LDSM4(al, sAloB + off);
            }
            #pragma unroll
            for (int n16 = 0; n16 < 6; n16++) {
                u32 bh[4], bl[4];
                int krow = ks + r + ((g & 1) << 3);
                int ncol = n16 * 16 + ((g >> 1) << 3);
                u32 off = (u32)(bb * 3328 + krow * 104 + ncol) * 2;
                LDSM4T(bh, sWhiB + off);
                LDSM4T(bl, sWloB + off);
                MMA16816(acc[n16 * 2], ah, (&bh[0]));
                MMA16816(acc[n16 * 2], ah, (&bl[0]));
                MMA16816(acc[n16 * 2], al, (&bh[0]));
                MMA16816(acc[n16 * 2 + 1], ah, (&bh[2]));
                MMA16816(acc[n16 * 2 + 1], ah, (&bl[2]));
                MMA16816(acc[n16 * 2 + 1], al, (&bh[2]));
            }
        }
        __syncthreads();
        if (it < 7) {
            storeTile(1 - bb);
            __syncthreads();
        }
    }
    // staging dead; epilogue writes plane overlay
    const float scale = 0.17677669529663687f;  // 1/sqrt(32)
    #pragma unroll
    for (int j = 0; j < 12; j++) {
        int colg = j * 8 + (lane & 3) * 2;
        int z = colg >> 5, c = colg & 31;
        const float* bz = (z == 0) ? bq : (z == 1) ? bk : bv;
        bf16* zhi = (z == 0) ? sQhi : (z == 1) ? sKhi : sVhi;
        bf16* zlo = (z == 0) ? sQlo : (z == 1) ? sKlo : sVlo;
        float scl = (z == 0) ? scale : 1.0f;
        float b0 = bz[h * 32 + c], b1 = bz[h * 32 + c + 1];
        #pragma unroll
        for (int half = 0; half < 2; half++) {
            int row = warp * 16 + (lane >> 2) + half * 8;
            float v0 = (acc[j][half * 2] + b0) * scl;
            float v1 = (acc[j][half * 2 + 1] + b1) * scl;
            u32 hi, lo;
            packP(v0, v1, hi, lo);
            *(u32*)&zhi[row * 40 + c] = hi;
            *(u32*)&zlo[row * 40 + c] = lo;
        }
    }
    __syncthreads();  // planes visible

    // ---- Phase 2: tensor-core attention ----
    // Q fragments for this warp's 16 rows (k=32 -> 2 k-tiles)
    u32 aQh[2][4], aQl[2][4];
    #pragma unroll
    for (int kt = 0; kt < 2; kt++) {
        int rowA = warp * 16 + r + ((g & 1) << 3);
        int kcol = kt * 16 + ((g >> 1) << 3);
        u32 off = (u32)(rowA * 40 + kcol) * 2;
        LDSM4(aQh[kt], sQhiB + off);
        LDSM4(aQl[kt], sQloB + off);
    }

    // S = Q K^T: 16 n8-tiles over 128 j
    float accS[16][4];
    #pragma unroll
    for (int nt = 0; nt < 16; nt++)
        #pragma unroll
        for (int i = 0; i < 4; i++) accS[nt][i] = 0.0f;

    #pragma unroll
    for (int kt = 0; kt < 2; kt++) {
        #pragma unroll
        for (int ng = 0; ng < 8; ng++) {
            u32 kbh[4], kbl[4];
            int nrow = ng * 16 + r + ((g & 1) << 3);
            int kcol = kt * 16 + ((g >> 1) << 3);
            u32 off = (u32)(nrow * 40 + kcol) * 2;
            LDSM4(kbh, sKhiB + off);   // B from [n][k]: frags {0,2},{1,3}
            LDSM4(kbl, sKloB + off);
            u32 b0h[2] = {kbh[0], kbh[2]}, b1h[2] = {kbh[1], kbh[3]};
            u32 b0l[2] = {kbl[0], kbl[2]}, b1l[2] = {kbl[1], kbl[3]};
            MMA16816(accS[ng * 2], aQh[kt], b0h);
            MMA16816(accS[ng * 2], aQh[kt], b0l);
            MMA16816(accS[ng * 2], aQl[kt], b0h);
            MMA16816(accS[ng * 2 + 1], aQh[kt], b1h);
            MMA16816(accS[ng * 2 + 1], aQh[kt], b1l);
            MMA16816(accS[ng * 2 + 1], aQl[kt], b1h);
        }
    }

    // mask
    int rA = warp * 16 + (lane >> 2);
    int rB = rA + 8;
    u32 mA[4], mB[4];
    #pragma unroll
    for (int w2 = 0; w2 < 4; w2++) { mA[w2] = cmask[rA * 4 + w2]; mB[w2] = cmask[rB * 4 + w2]; }
    #pragma unroll
    for (int nt = 0; nt < 16; nt++) {
        int c0 = nt * 8 + (lane & 3) * 2;
        int w2 = c0 >> 5, bit = c0 & 31;
        if (!((mA[w2] >> bit) & 1u))       accS[nt][0] = -INFINITY;
        if (!((mA[w2] >> (bit + 1)) & 1u)) accS[nt][1] = -INFINITY;
        if (!((mB[w2] >> bit) & 1u))       accS[nt][2] = -INFINITY;
        if (!((mB[w2] >> (bit + 1)) & 1u)) accS[nt][3] = -INFINITY;
    }

    // row max (4 lanes per row)
    float mxA = -INFINITY, mxB = -INFINITY;
    #pragma unroll
    for (int nt = 0; nt < 16; nt++) {
        mxA = fmaxf(mxA, fmaxf(accS[nt][0], accS[nt][1]));
        mxB = fmaxf(mxB, fmaxf(accS[nt][2], accS[nt][3]));
    }
    mxA = fmaxf(mxA, __shfl_xor_sync(0xffffffffu, mxA, 1));
    mxA = fmaxf(mxA, __shfl_xor_sync(0xffffffffu, mxA, 2));
    mxB = fmaxf(mxB, __shfl_xor_sync(0xffffffffu, mxB, 1));
    mxB = fmaxf(mxB, __shfl_xor_sync(0xffffffffu, mxB, 2));

    // exp + sums
    float sA = 0.0f, sB = 0.0f;
    #pragma unroll
    for (int nt = 0; nt < 16; nt++) {
        accS[nt][0] = expf(accS[nt][0] - mxA);
        accS[nt][1] = expf(accS[nt][1] - mxA);
        accS[nt][2] = expf(accS[nt][2] - mxB);
        accS[nt][3] = expf(accS[nt][3] - mxB);
        sA += accS[nt][0] + accS[nt][1];
        sB += accS[nt][2] + accS[nt][3];
    }
    sA += __shfl_xor_sync(0xffffffffu, sA, 1);
    sA += __shfl_xor_sync(0xffffffffu, sA, 2);
    sB += __shfl_xor_sync(0xffffffffu, sB, 1);
    sB += __shfl_xor_sync(0xffffffffu, sB, 2);
    float invA = 1.0f / sA, invB = 1.0f / sB;

    // O = P V  (P split-bf16 A-frags from accS; V^T B-frags via trans ldmatrix)
    float accO[4][4];
    #pragma unroll
    for (int nt = 0; nt < 4; nt++)
        #pragma unroll
        for (int i = 0; i < 4; i++) accO[nt][i] = 0.0f;

    #pragma unroll
    for (int kt = 0; kt < 8; kt++) {
        u32 ph[4], plo[4];
        packP(accS[2 * kt][0],     accS[2 * kt][1],     ph[0], plo[0]);
        packP(accS[2 * kt][2],     accS[2 * kt][3],     ph[1], plo[1]);
        packP(accS[2 * kt + 1][0], accS[2 * kt + 1][1], ph[2], plo[2]);
        packP(accS[2 * kt + 1][2], accS[2 * kt + 1][3], ph[3], plo[3]);
        #pragma unroll
        for (int n16 = 0; n16 < 2; n16++) {
            u32 vbh[4], vbl[4];
            int krow = kt * 16 + r + ((g & 1) << 3);
            int ncol = n16 * 16 + ((g >> 1) << 3);
            u32 off = (u32)(krow * 40 + ncol) * 2;
            LDSM4T(vbh, sVhiB + off);
            LDSM4T(vbl, sVloB + off);
            MMA16816(accO[n16 * 2], ph, (&vbh[0]));
            MMA16816(accO[n16 * 2], ph, (&vbl[0]));
            MMA16816(accO[n16 * 2], plo, (&vbh[0]));
            MMA16816(accO[n16 * 2 + 1], ph, (&vbh[2]));
            MMA16816(accO[n16 * 2 + 1], ph, (&vbl[2]));
            MMA16816(accO[n16 * 2 + 1], plo, (&vbh[2]));
        }
    }

    // write O -> ao planes
    #pragma unroll
    for (int nt = 0; nt < 4; nt++) {
        int c0 = nt * 8 + (lane & 3) * 2;
        int oA = (b * 128 + rA) * 256 + h * 32 + c0;
        int oB = (b * 128 + rB) * 256 + h * 32 + c0;
        u32 hi, lo;
        packP(accO[nt][0] * invA, accO[nt][1] * invA, hi, lo);
        *(u32*)&g_aohi[oA] = hi; *(u32*)&g_aolo[oA] = lo;
        packP(accO[nt][2] * invB, accO[nt][3] * invB, hi, lo);
        *(u32*)&g_aohi[oB] = hi; *(u32*)&g_aolo[oB] = lo;
    }
}

// ---------------- launch ------------------------------------------------------
extern "C" void kernel_launch(void* const* d_in, const int* in_sizes, int n_in,
                              void* d_out, int out_size)
{
    const float* x        = (const float*)d_in[0];
    const float* gumbel_u = (const float*)d_in[1];
    const float* memory_w = (const float*)d_in[2];
    const float* fc_out_w = (const float*)d_in[3];
    const float* fc_out_b = (const float*)d_in[4];
    const float* fc_cat_w = (const float*)d_in[5];
    const float* fc_cat_b = (const float*)d_in[6];
    const float* wq       = (const float*)d_in[7];
    const float* bq       = (const float*)d_in[8];
    const float* wk       = (const float*)d_in[9];
    const float* bk       = (const float*)d_in[10];
    const float* wv       = (const float*)d_in[11];
    const float* bv       = (const float*)d_in[12];
    const float* out_w    = (const float*)d_in[13];
    const float* out_b    = (const float*)d_in[14];
    const float* mlp_w1   = (const float*)d_in[15];
    const float* mlp_b1   = (const float*)d_in[16];
    const float* mlp_w2   = (const float*)d_in[17];
    const float* mlp_b2   = (const float*)d_in[18];

    float *fA, *fB;
    cudaGetSymbolAddress((void**)&fA, g_fA);
    cudaGetSymbolAddress((void**)&fB, g_fB);
    bf16 *h1hi, *h1lo, *xmhi, *xmlo, *aohi, *aolo;
    cudaGetSymbolAddress((void**)&h1hi, g_h1hi);
    cudaGetSymbolAddress((void**)&h1lo, g_h1lo);
    cudaGetSymbolAddress((void**)&xmhi, g_xmhi);
    cudaGetSymbolAddress((void**)&xmlo, g_xmlo);
    cudaGetSymbolAddress((void**)&aohi, g_aohi);
    cudaGetSymbolAddress((void**)&aolo, g_aolo);

    static bool attrSet = false;
    if (!attrSet) {
        cudaFuncSetAttribute(k_qkv_attn, cudaFuncAttributeMaxDynamicSharedMemorySize, QKV_SMEM);
        attrSet = true;
    }

    Job JZ = {};
    ConnArgs CA = { fc_out_b, fc_cat_w, fc_cat_b, gumbel_u };

    // L1: fA (128 tiles) + fB (128) + mlp1 (512)
    {
        Job ja = JZ, jb = JZ, jm = JZ;
        ja.Af = memory_w; ja.Wf = fc_out_w;         ja.Cf = fA; ja.aMode = 1;
        jb.Af = memory_w; jb.Wf = fc_out_w + 65536; jb.Cf = fB; jb.aMode = 1;
        jm.Af = x; jm.Wf = mlp_w1; jm.bias = mlp_b1;
        jm.Chi = h1hi; jm.Clo = h1lo; jm.aMode = 0; jm.act = 1; jm.storeMode = 1;
        k_gemm32<<<768, 256>>>(ja, jb, jm, 128, 256, 768, CA);
    }

    // L2: mlp2 (512 tiles) + conn (128 jobs)
    {
        Job j = JZ;
        j.Ahi = h1hi; j.Alo = h1lo; j.Wf = mlp_w2; j.bias = mlp_b2;
        j.Chi = xmhi; j.Clo = xmlo; j.aMode = 2; j.storeMode = 1;
        k_gemm32<<<640, 256>>>(j, JZ, JZ, 512, 512, 512, CA);
    }

    // L3: fused QKV + tensor-core attention (256 CTAs, one per (b,h))
    k_qkv_attn<<<256, 256, QKV_SMEM>>>(wq, bq, wk, bk, wv, bv);

    // L4: output projection -> d_out
    {
        Job j = JZ;
        j.Ahi = aohi; j.Alo = aolo; j.Wf = out_w; j.bias = out_b;
        j.Cf = (float*)d_out; j.aMode = 2; j.storeMode = 0;
        k_gemm32<<<512, 256>>>(j, JZ, JZ, 512, 512, 512, CA);
    }
}